// round 15
// baseline (speedup 1.0000x reference)
#include <cuda_runtime.h>
#include <math.h>

#define BATCH 32
#define PRI   8732
#define NCLS_TOT 81
#define NCLS  80
#define NTASK (BATCH * NCLS)
#define KTOP  200
#define CONF_TH 0.01f
#define NMS_TH  0.45f
#define CAND_MAX 1024
#define CAND2   256
#define NBINS 4096
#define PRE_BITS 0x3F780000u     // 0.96875f prefilter: ~273 cands/task (4.5 sigma > K)
#define ONE_BITS 0x3F800000u
#define NP_CHUNK 192             // priors per filter block (46 * 192 >= 8732; np % 4 == 0)
#define NCHUNK 46
#define FCAP 32

// Scratch (__device__ globals; no allocation allowed)
__device__ float4 g_boxes[BATCH * PRI];
__device__ unsigned long long g_cand[(size_t)NTASK * CAND_MAX];
__device__ unsigned g_count[NTASK];

// ---------------------------------------------------------------------------
// Fused: decode boxes + zero per-task counters + zero background slabs.
// ---------------------------------------------------------------------------
__global__ void prep_kernel(const float4* __restrict__ loc,
                            const float4* __restrict__ priors,
                            float* __restrict__ out) {
    int i = blockIdx.x * blockDim.x + threadIdx.x;
    if (i < NTASK) g_count[i] = 0;
    if (i < BATCH * KTOP * 5) {
        int b = i / (KTOP * 5);
        int r = i % (KTOP * 5);
        out[(size_t)b * NCLS_TOT * KTOP * 5 + r] = 0.0f;
    }
    if (i < BATCH * PRI) {
        int p = i % PRI;
        float4 l  = loc[i];
        float4 pr = priors[p];
        float cx = pr.x + (l.x * 0.1f) * pr.z;
        float cy = pr.y + (l.y * 0.1f) * pr.w;
        float w  = pr.z * expf(l.z * 0.2f);
        float h  = pr.w * expf(l.w * 0.2f);
        float x1 = cx - w * 0.5f;
        float y1 = cy - h * 0.5f;
        g_boxes[i] = make_float4(x1, y1, x1 + w, y1 + h);
    }
}

// ---------------------------------------------------------------------------
// Filter: 4x-batched uint4 loads (MLP), smem staging, bulk drain (as R14).
// ---------------------------------------------------------------------------
__device__ __forceinline__ void filter_process(
    uint4 v, int e4, int b, int p0,
    unsigned long long* stage, unsigned* scount) {
    unsigned mx = max(max(v.x, v.y), max(v.z, v.w));
    if (mx >= PRE_BITS) {
        #pragma unroll
        for (int k = 0; k < 4; k++) {
            unsigned bits = (k == 0) ? v.x : (k == 1) ? v.y : (k == 2) ? v.z : v.w;
            if ((int)bits >= (int)PRE_BITS) {
                unsigned eloc = (unsigned)(e4 << 2) + k;
                unsigned row  = eloc / NCLS_TOT;
                unsigned c    = eloc - row * NCLS_TOT;
                if (c != 0u) {
                    unsigned p = (unsigned)p0 + row;
                    int cls = (int)c - 1;
                    unsigned long long key =
                        ((unsigned long long)bits << 32) | (unsigned)(~p);
                    unsigned pos = atomicAdd(&scount[cls], 1u);
                    if (pos < FCAP) {
                        stage[cls * FCAP + pos] = key;
                    } else {
                        int task = b * NCLS + cls;
                        unsigned g = atomicAdd(&g_count[task], 1u);
                        if (g < CAND_MAX) g_cand[(size_t)task * CAND_MAX + g] = key;
                    }
                }
            }
        }
    }
}

__global__ void __launch_bounds__(256) filter_kernel(const unsigned* __restrict__ conf) {
    __shared__ unsigned long long stage[NCLS * FCAP];   // 20 KB
    __shared__ unsigned scount[NCLS];

    const int chunk = blockIdx.x;
    const int b     = blockIdx.y;
    const int p0    = chunk * NP_CHUNK;
    const int tid   = threadIdx.x;
    const int lane  = tid & 31;
    const int wid   = tid >> 5;

    for (int t = tid; t < NCLS; t += 256) scount[t] = 0;
    __syncthreads();

    const int np     = min(NP_CHUNK, PRI - p0);
    const int limit4 = (np * NCLS_TOT) >> 2;
    const uint4* base4 = (const uint4*)(conf + ((size_t)b * PRI + p0) * NCLS_TOT);

    int e4 = tid;
    for (; e4 + 768 < limit4; e4 += 1024) {
        uint4 v0 = base4[e4];
        uint4 v1 = base4[e4 + 256];
        uint4 v2 = base4[e4 + 512];
        uint4 v3 = base4[e4 + 768];
        filter_process(v0, e4,       b, p0, stage, scount);
        filter_process(v1, e4 + 256, b, p0, stage, scount);
        filter_process(v2, e4 + 512, b, p0, stage, scount);
        filter_process(v3, e4 + 768, b, p0, stage, scount);
    }
    for (; e4 < limit4; e4 += 256)
        filter_process(base4[e4], e4, b, p0, stage, scount);
    __syncthreads();

    for (int cls = wid; cls < NCLS; cls += 8) {
        unsigned cnt = min(scount[cls], (unsigned)FCAP);
        if (cnt == 0) continue;
        int task = b * NCLS + cls;
        unsigned bse = 0;
        if (lane == 0) bse = atomicAdd(&g_count[task], cnt);
        bse = __shfl_sync(0xFFFFFFFFu, bse, 0);
        if (lane < cnt) {
            unsigned pos = bse + lane;
            if (pos < CAND_MAX)
                g_cand[(size_t)task * CAND_MAX + pos] = stage[cls * FCAP + lane];
        }
    }
}

// ---------------------------------------------------------------------------
__device__ __forceinline__ unsigned suffix_incl_256(unsigned part, unsigned* warpTot,
                                                    int lane, int wid) {
    unsigned v = part;
    #pragma unroll
    for (int d = 1; d < 32; d <<= 1) {
        unsigned o = __shfl_down_sync(0xFFFFFFFFu, v, d);
        v += (lane < 32 - d) ? o : 0u;
    }
    if (lane == 0) warpTot[wid] = v;
    __syncthreads();
    unsigned add = 0;
    #pragma unroll
    for (int q = 0; q < 8; q++) add += (q > wid) ? warpTot[q] : 0u;
    return v + add;
}

// ---------------------------------------------------------------------------
// Build suppression-mask rows for chunk c (rows [c*64, min(n,c*64+64))),
// distributed over numWarps warps (warpIdx in [0,numWarps)). w-outer form:
// bj pinned in registers per word, 4 rows per inner group. All ballots
// warp-uniform. Words below the chunk's start word stay pre-zeroed (they
// hold only j<=i bits, which greedy never sets).
// ---------------------------------------------------------------------------
__device__ __forceinline__ void build_chunk_masks(
    int c, int n, int wEnd, float Tp1,
    const float4* sBox, const float* sTArea, unsigned* maskW,
    int warpIdx, int numWarps, int lane) {
    const int base = c * 64;
    const int end  = min(n, base + 64);
    const int wS   = (base + 1) >> 5;
    for (int w = wS; w < wEnd; w++) {
        const int j = w * 32 + lane;
        const bool jv = (j < n);
        float4 bj = make_float4(0.f, 0.f, 0.f, 0.f);
        float nTj = 0.f;
        if (jv) { bj = sBox[j]; nTj = -sTArea[j]; }
        const int iMax = min(end, w * 32 + 32);
        for (int i0 = base + warpIdx * 4; i0 < iMax; i0 += numWarps * 4) {
            #pragma unroll
            for (int r = 0; r < 4; r++) {
                const int i = i0 + r;
                const bool iv = (i < iMax);
                bool sup = false;
                if (iv) {
                    float4 bi = sBox[i];
                    float nTi = -sTArea[i];
                    if (jv && j > i) {
                        float ww = fminf(bi.z, bj.z) - fmaxf(bi.x, bj.x);
                        float hh = fminf(bi.w, bj.w) - fmaxf(bi.y, bj.y);
                        ww = fmaxf(ww, 0.0f); hh = fmaxf(hh, 0.0f);
                        sup = fmaf(ww * hh, Tp1, nTi + nTj) > 0.0f;
                    }
                }
                unsigned bal = __ballot_sync(0xFFFFFFFFu, sup);
                if (lane == 0 && iv) maskW[i * 8 + w] = bal;
            }
        }
    }
}

// ---------------------------------------------------------------------------
__global__ void __launch_bounds__(256, 8) nms_kernel(const unsigned* __restrict__ conf,
                                                     float* __restrict__ out) {
    __shared__ unsigned histM[NBINS];
    __shared__ unsigned long long buf[CAND_MAX];
    __shared__ unsigned warpTot[8];
    __shared__ unsigned long long sKeepW[4];
    __shared__ unsigned s_binT, s_above, s_fcut, s_aboveF, s_cntF, s_f2cut, s_n2, s_gc, s_bad;
    __shared__ int s_found;

    unsigned long long* cand2 = (unsigned long long*)histM;
    float4* sBox   = (float4*)(histM + 512);
    float*  sScore = (float*)(histM + 1312);
    float*  sTArea = (float*)(histM + 1512);
    unsigned* maskW = (unsigned*)buf;                     // [KTOP][8] u32

    const int task = blockIdx.x;
    const int b    = task / NCLS;
    const int cc   = task % NCLS;
    const int tid  = threadIdx.x;
    const int wid  = tid >> 5;
    const int lane = tid & 31;

    if (tid == 0) {
        s_found = 0; s_binT = 0; s_above = 0; s_fcut = 0;
        s_aboveF = 0; s_cntF = 0; s_f2cut = 0; s_n2 = 0; s_gc = 0; s_bad = 0;
    }
    __syncthreads();

    const unsigned gc0 = g_count[task];
    const bool fastCnt = (gc0 >= KTOP && gc0 <= CAND_MAX);
    int gcount = 0;

    if (fastCnt) {
        const unsigned long long* src = g_cand + (size_t)task * CAND_MAX;
        unsigned bad = 0;
        for (int t = tid; t < (int)gc0; t += 256) {
            unsigned long long key = src[t];
            buf[t] = key;
            bad |= ((unsigned)(key >> 32) >= ONE_BITS) ? 1u : 0u;
        }
        if (__any_sync(0xFFFFFFFFu, bad) && lane == 0) atomicOr(&s_bad, 1u);
    }
    __syncthreads();
    const bool fast = fastCnt && (s_bad == 0);

    if (fast) {
        if (tid == 0) { s_binT = PRE_BITS >> 20; s_above = 0; s_found = 1; }
        gcount = (int)gc0;
        histM[tid] = 0;
        __syncthreads();
    } else {
        for (int t = tid; t < NBINS; t += 256) histM[t] = 0;
        __syncthreads();
        const unsigned* col = conf + (size_t)b * PRI * NCLS_TOT + (cc + 1);
        for (int p = tid; p < PRI; p += 256) {
            unsigned bits = col[(size_t)p * NCLS_TOT];
            if (__uint_as_float(bits) > CONF_TH) atomicAdd(&histM[bits >> 20], 1u);
        }
        __syncthreads();
        unsigned part = 0;
        #pragma unroll
        for (int r = 0; r < 16; r++) part += histM[tid * 16 + r];
        unsigned incl = suffix_incl_256(part, warpTot, lane, wid);
        unsigned excl = incl - part;
        if (excl < KTOP && incl >= KTOP) {
            unsigned cum = excl;
            for (int bb = tid * 16 + 15; bb >= tid * 16; bb--) {
                cum += histM[bb];
                if (cum >= KTOP) {
                    s_binT = (unsigned)bb; s_above = cum - histM[bb]; s_found = 1;
                    break;
                }
            }
        }
        __syncthreads();
        const unsigned bT = s_binT;
        for (int p = tid; p < PRI; p += 256) {
            unsigned bits = col[(size_t)p * NCLS_TOT];
            if (__uint_as_float(bits) > CONF_TH && (bits >> 20) >= bT) {
                unsigned pos = atomicAdd(&s_gc, 1u);
                if (pos < CAND_MAX)
                    buf[pos] = ((unsigned long long)bits << 32) | (unsigned)(~(unsigned)p);
            }
        }
        __syncthreads();
        gcount = (int)min(s_gc, (unsigned)CAND_MAX);
        histM[tid] = 0;
        __syncthreads();
    }

    const int found = s_found;
    const unsigned binT = s_binT;
    const unsigned need = KTOP - s_above;
    const bool skipRef = fast && (gcount <= CAND2);   // all cands fit the sort

    // ---- fine refinement: bits[19:12] within cut bin ----
    if (found && !skipRef) {
        for (int t = tid; t < gcount; t += 256) {
            unsigned long long key = buf[t];
            if ((unsigned)(key >> 52) == binT)
                atomicAdd(&histM[(unsigned)(key >> 44) & 0xFFu], 1u);
        }
        __syncthreads();
        unsigned part = histM[tid];
        unsigned incl = suffix_incl_256(part, warpTot, lane, wid);
        unsigned excl = incl - part;
        if (excl < need && incl >= need) {
            s_fcut = (unsigned)tid; s_aboveF = excl; s_cntF = part;
        }
        __syncthreads();
    }
    const unsigned fcut = s_fcut;                     // 0 when skipRef

    // ---- optional fine2 on bits[11:4] ----
    if (found && !skipRef && (s_aboveF + s_cntF > CAND2)) {
        const unsigned need2 = need - s_aboveF;
        histM[tid] = 0;
        __syncthreads();
        for (int t = tid; t < gcount; t += 256) {
            unsigned long long key = buf[t];
            if ((unsigned)(key >> 52) == binT &&
                ((unsigned)(key >> 44) & 0xFFu) == fcut)
                atomicAdd(&histM[(unsigned)(key >> 36) & 0xFFu], 1u);
        }
        __syncthreads();
        unsigned part = histM[tid];
        unsigned incl = suffix_incl_256(part, warpTot, lane, wid);
        unsigned excl = incl - part;
        if (excl < need2 && incl >= need2) s_f2cut = (unsigned)tid;
        __syncthreads();
    }
    const unsigned f2cut = s_f2cut;
    __syncthreads();

    // ---- compact refined candidates into cand2 ----
    cand2[tid] = 0ULL;
    __syncthreads();
    for (int t = tid; t < gcount; t += 256) {
        unsigned long long key = buf[t];
        unsigned cb = (unsigned)(key >> 52);
        unsigned fb = (unsigned)(key >> 44) & 0xFFu;
        unsigned f2 = (unsigned)(key >> 36) & 0xFFu;
        if (cb > binT ||
            (cb == binT && (fb > fcut || (fb == fcut && f2 >= f2cut)))) {
            unsigned pos = atomicAdd(&s_n2, 1u);
            if (pos < CAND2) cand2[pos] = key;
        }
    }
    __syncthreads();
    const int n = min((int)min(s_n2, (unsigned)CAND2), KTOP);

    // ---- register bitonic sort (asc) ----
    unsigned long long key = cand2[tid];
    for (int kk = 2; kk <= 256; kk <<= 1) {
        bool up = ((tid & kk) == 0);
        for (int jj = kk >> 1; jj > 0; jj >>= 1) {
            unsigned long long partner;
            if (jj >= 32) {
                __syncthreads();
                cand2[tid] = key;
                __syncthreads();
                partner = cand2[tid ^ jj];
            } else {
                partner = __shfl_xor_sync(0xFFFFFFFFu, key, jj);
            }
            bool takeMin = (((tid & jj) == 0) == up);
            bool sw = takeMin ? (partner < key) : (partner > key);
            if (sw) key = partner;
        }
    }
    __syncthreads();

    // ---- extract top-n (descending); zero mask rows; init keep words ----
    {
        int k = 255 - tid;
        if (k < n) {
            unsigned bits = (unsigned)(key >> 32);
            int p = (int)(~(unsigned)key);
            float4 bx = g_boxes[b * PRI + p];
            sBox[k]   = bx;
            sScore[k] = __uint_as_float(bits);
            sTArea[k] = NMS_TH * (bx.z - bx.x) * (bx.w - bx.y);
        }
        for (int t = tid; t < n * 8; t += 256) maskW[t] = 0u;
        if (tid < 4) {
            int rem = n - tid * 64;
            sKeepW[tid] = (rem >= 64) ? ~0ULL : (rem > 0 ? ((1ULL << rem) - 1ULL) : 0ULL);
        }
    }
    __syncthreads();

    // ---- pipelined chunked NMS: scan chunk q || build chunk q+1 ----
    const int wEnd = (n + 31) >> 5;
    const int nCh  = (n + 63) >> 6;
    const float Tp1 = 1.0f + NMS_TH;
    float* outBase = out + (size_t)(b * NCLS_TOT + cc + 1) * KTOP * 5;
    float4* outBase4 = (float4*)outBase;

    if (nCh == 0) {
        // no candidates: keep words already 0; just zero the slab
        for (int t = tid; t < KTOP * 5 / 4; t += 256)
            outBase4[t] = make_float4(0.f, 0.f, 0.f, 0.f);
        __syncthreads();
    } else {
        // phase 0: all 8 warps build chunk-0 masks
        build_chunk_masks(0, n, wEnd, Tp1, sBox, sTArea, maskW, wid, 8, lane);
        __syncthreads();

        const unsigned long long* m64 = (const unsigned long long*)maskW;
        for (int q = 0; q < nCh; q++) {
            if (wid == 0) {
                if (lane == 0) {
                    unsigned long long k0 = sKeepW[0], k1 = sKeepW[1];
                    unsigned long long k2 = sKeepW[2], k3 = sKeepW[3];
                    unsigned long long w =
                        (q == 0) ? k0 : (q == 1) ? k1 : (q == 2) ? k2 : k3;
                    while (w) {
                        int bit = __ffsll((long long)w) - 1;
                        int i = q * 64 + bit;
                        k0 &= ~m64[i * 4 + 0]; k1 &= ~m64[i * 4 + 1];
                        k2 &= ~m64[i * 4 + 2]; k3 &= ~m64[i * 4 + 3];
                        unsigned long long cur =
                            (q == 0) ? k0 : (q == 1) ? k1 : (q == 2) ? k2 : k3;
                        unsigned long long hi =
                            (bit == 63) ? 0ULL : (~0ULL << (bit + 1));
                        w = cur & hi;
                    }
                    sKeepW[0] = k0; sKeepW[1] = k1; sKeepW[2] = k2; sKeepW[3] = k3;
                }
            } else {
                if (q + 1 < nCh) {
                    build_chunk_masks(q + 1, n, wEnd, Tp1, sBox, sTArea, maskW,
                                      wid - 1, 7, lane);
                } else {
                    // last phase: warps 1-7 zero the output slab
                    for (int t = tid - 32; t < KTOP * 5 / 4; t += 224)
                        outBase4[t] = make_float4(0.f, 0.f, 0.f, 0.f);
                }
            }
            __syncthreads();
        }
    }

    // ---- scatter kept rows to front ----
    for (int k = tid; k < n; k += 256) {
        unsigned long long w = sKeepW[k >> 6];
        if ((w >> (k & 63)) & 1ULL) {
            int d = 0;
            for (int q = 0; q < (k >> 6); q++) d += __popcll(sKeepW[q]);
            unsigned long long below = (k & 63) ? (w & ((1ULL << (k & 63)) - 1ULL)) : 0ULL;
            d += __popcll(below);
            float* r = outBase + d * 5;
            float4 bx = sBox[k];
            r[0] = sScore[k];
            r[1] = bx.x; r[2] = bx.y; r[3] = bx.z; r[4] = bx.w;
        }
    }
}

// ---------------------------------------------------------------------------
extern "C" void kernel_launch(void* const* d_in, const int* in_sizes, int n_in,
                              void* d_out, int out_size) {
    const float4*   loc   = (const float4*)d_in[0];     // [B, P, 4]
    const unsigned* conf  = (const unsigned*)d_in[1];   // [B*P, C] (float bits)
    const float4*   prior = (const float4*)d_in[2];     // [P, 4]
    float* out = (float*)d_out;                         // [B, C, K, 5]

    prep_kernel<<<(BATCH * PRI + 255) / 256, 256>>>(loc, prior, out);

    dim3 fg(NCHUNK, BATCH);
    filter_kernel<<<fg, 256>>>(conf);

    nms_kernel<<<NTASK, 256>>>(conf, out);
}

// round 16
// speedup vs baseline: 1.0291x; 1.0291x over previous
#include <cuda_runtime.h>
#include <math.h>

#define BATCH 32
#define PRI   8732
#define NCLS_TOT 81
#define NCLS  80
#define NTASK (BATCH * NCLS)
#define KTOP  200
#define CONF_TH 0.01f
#define NMS_TH  0.45f
#define CAND_MAX 1024
#define CAND2   256
#define NBINS 4096
#define PRE_BITS 0x3F780000u     // 0.96875f prefilter: ~273 cands/task (4.5 sigma > K)
#define ONE_BITS 0x3F800000u
#define NP_CHUNK 192             // priors per filter block (46 * 192 >= 8732; np % 4 == 0)
#define NCHUNK 46
#define FCAP 32

// Scratch (__device__ globals; no allocation allowed)
__device__ float4 g_boxes[BATCH * PRI];
__device__ unsigned long long g_cand[(size_t)NTASK * CAND_MAX];
__device__ unsigned g_count[NTASK];

// ---------------------------------------------------------------------------
// Fused: decode boxes + zero per-task counters + zero background slabs.
// ---------------------------------------------------------------------------
__global__ void prep_kernel(const float4* __restrict__ loc,
                            const float4* __restrict__ priors,
                            float* __restrict__ out) {
    int i = blockIdx.x * blockDim.x + threadIdx.x;
    if (i < NTASK) g_count[i] = 0;
    if (i < BATCH * KTOP * 5) {
        int b = i / (KTOP * 5);
        int r = i % (KTOP * 5);
        out[(size_t)b * NCLS_TOT * KTOP * 5 + r] = 0.0f;
    }
    if (i < BATCH * PRI) {
        int p = i % PRI;
        float4 l  = loc[i];
        float4 pr = priors[p];
        float cx = pr.x + (l.x * 0.1f) * pr.z;
        float cy = pr.y + (l.y * 0.1f) * pr.w;
        float w  = pr.z * expf(l.z * 0.2f);
        float h  = pr.w * expf(l.w * 0.2f);
        float x1 = cx - w * 0.5f;
        float y1 = cy - h * 0.5f;
        g_boxes[i] = make_float4(x1, y1, x1 + w, y1 + h);
    }
}

// ---------------------------------------------------------------------------
// Filter: 4x-batched uint4 loads (MLP), smem staging, bulk drain (as R14).
// ---------------------------------------------------------------------------
__device__ __forceinline__ void filter_process(
    uint4 v, int e4, int b, int p0,
    unsigned long long* stage, unsigned* scount) {
    unsigned mx = max(max(v.x, v.y), max(v.z, v.w));
    if (mx >= PRE_BITS) {
        #pragma unroll
        for (int k = 0; k < 4; k++) {
            unsigned bits = (k == 0) ? v.x : (k == 1) ? v.y : (k == 2) ? v.z : v.w;
            if ((int)bits >= (int)PRE_BITS) {
                unsigned eloc = (unsigned)(e4 << 2) + k;
                unsigned row  = eloc / NCLS_TOT;
                unsigned c    = eloc - row * NCLS_TOT;
                if (c != 0u) {
                    unsigned p = (unsigned)p0 + row;
                    int cls = (int)c - 1;
                    unsigned long long key =
                        ((unsigned long long)bits << 32) | (unsigned)(~p);
                    unsigned pos = atomicAdd(&scount[cls], 1u);
                    if (pos < FCAP) {
                        stage[cls * FCAP + pos] = key;
                    } else {
                        int task = b * NCLS + cls;
                        unsigned g = atomicAdd(&g_count[task], 1u);
                        if (g < CAND_MAX) g_cand[(size_t)task * CAND_MAX + g] = key;
                    }
                }
            }
        }
    }
}

__global__ void __launch_bounds__(256) filter_kernel(const unsigned* __restrict__ conf) {
    __shared__ unsigned long long stage[NCLS * FCAP];   // 20 KB
    __shared__ unsigned scount[NCLS];

    const int chunk = blockIdx.x;
    const int b     = blockIdx.y;
    const int p0    = chunk * NP_CHUNK;
    const int tid   = threadIdx.x;
    const int lane  = tid & 31;
    const int wid   = tid >> 5;

    for (int t = tid; t < NCLS; t += 256) scount[t] = 0;
    __syncthreads();

    const int np     = min(NP_CHUNK, PRI - p0);
    const int limit4 = (np * NCLS_TOT) >> 2;
    const uint4* base4 = (const uint4*)(conf + ((size_t)b * PRI + p0) * NCLS_TOT);

    int e4 = tid;
    for (; e4 + 768 < limit4; e4 += 1024) {
        uint4 v0 = base4[e4];
        uint4 v1 = base4[e4 + 256];
        uint4 v2 = base4[e4 + 512];
        uint4 v3 = base4[e4 + 768];
        filter_process(v0, e4,       b, p0, stage, scount);
        filter_process(v1, e4 + 256, b, p0, stage, scount);
        filter_process(v2, e4 + 512, b, p0, stage, scount);
        filter_process(v3, e4 + 768, b, p0, stage, scount);
    }
    for (; e4 < limit4; e4 += 256)
        filter_process(base4[e4], e4, b, p0, stage, scount);
    __syncthreads();

    for (int cls = wid; cls < NCLS; cls += 8) {
        unsigned cnt = min(scount[cls], (unsigned)FCAP);
        if (cnt == 0) continue;
        int task = b * NCLS + cls;
        unsigned bse = 0;
        if (lane == 0) bse = atomicAdd(&g_count[task], cnt);
        bse = __shfl_sync(0xFFFFFFFFu, bse, 0);
        if (lane < cnt) {
            unsigned pos = bse + lane;
            if (pos < CAND_MAX)
                g_cand[(size_t)task * CAND_MAX + pos] = stage[cls * FCAP + lane];
        }
    }
}

// ---------------------------------------------------------------------------
__device__ __forceinline__ unsigned suffix_incl_256(unsigned part, unsigned* warpTot,
                                                    int lane, int wid) {
    unsigned v = part;
    #pragma unroll
    for (int d = 1; d < 32; d <<= 1) {
        unsigned o = __shfl_down_sync(0xFFFFFFFFu, v, d);
        v += (lane < 32 - d) ? o : 0u;
    }
    if (lane == 0) warpTot[wid] = v;
    __syncthreads();
    unsigned add = 0;
    #pragma unroll
    for (int q = 0; q < 8; q++) add += (q > wid) ? warpTot[q] : 0u;
    return v + add;
}

// ---------------------------------------------------------------------------
// nms_kernel: R14 structure (best measured at 166.3us) + skipRef shortcut.
// ---------------------------------------------------------------------------
__global__ void __launch_bounds__(256, 8) nms_kernel(const unsigned* __restrict__ conf,
                                                     float* __restrict__ out) {
    __shared__ unsigned histM[NBINS];
    __shared__ unsigned long long buf[CAND_MAX];
    __shared__ unsigned warpTot[8];
    __shared__ unsigned long long sKeepW[4];
    __shared__ unsigned s_binT, s_above, s_fcut, s_aboveF, s_cntF, s_f2cut, s_n2, s_gc, s_bad;
    __shared__ int s_found;

    unsigned long long* cand2 = (unsigned long long*)histM;
    float4* sBox   = (float4*)(histM + 512);
    float*  sScore = (float*)(histM + 1312);
    float*  sTArea = (float*)(histM + 1512);
    unsigned* maskW = (unsigned*)buf;                     // [KTOP][8] u32

    const int task = blockIdx.x;
    const int b    = task / NCLS;
    const int cc   = task % NCLS;
    const int tid  = threadIdx.x;
    const int wid  = tid >> 5;
    const int lane = tid & 31;

    if (tid == 0) {
        s_found = 0; s_binT = 0; s_above = 0; s_fcut = 0;
        s_aboveF = 0; s_cntF = 0; s_f2cut = 0; s_n2 = 0; s_gc = 0; s_bad = 0;
    }
    __syncthreads();

    const unsigned gc0 = g_count[task];
    const bool fastCnt = (gc0 >= KTOP && gc0 <= CAND_MAX);
    int gcount = 0;

    if (fastCnt) {
        const unsigned long long* src = g_cand + (size_t)task * CAND_MAX;
        unsigned bad = 0;
        for (int t = tid; t < (int)gc0; t += 256) {
            unsigned long long key = src[t];
            buf[t] = key;
            bad |= ((unsigned)(key >> 32) >= ONE_BITS) ? 1u : 0u;
        }
        if (__any_sync(0xFFFFFFFFu, bad) && lane == 0) atomicOr(&s_bad, 1u);
    }
    __syncthreads();
    const bool fast = fastCnt && (s_bad == 0);
    const bool skipRef = fast && (gc0 <= CAND2);      // all cands fit the sort

    if (fast) {
        if (tid == 0) { s_binT = PRE_BITS >> 20; s_above = 0; s_found = 1; }
        gcount = (int)gc0;
        if (!skipRef) histM[tid] = 0;
        __syncthreads();
    } else {
        for (int t = tid; t < NBINS; t += 256) histM[t] = 0;
        __syncthreads();
        const unsigned* col = conf + (size_t)b * PRI * NCLS_TOT + (cc + 1);
        for (int p = tid; p < PRI; p += 256) {
            unsigned bits = col[(size_t)p * NCLS_TOT];
            if (__uint_as_float(bits) > CONF_TH) atomicAdd(&histM[bits >> 20], 1u);
        }
        __syncthreads();
        unsigned part = 0;
        #pragma unroll
        for (int r = 0; r < 16; r++) part += histM[tid * 16 + r];
        unsigned incl = suffix_incl_256(part, warpTot, lane, wid);
        unsigned excl = incl - part;
        if (excl < KTOP && incl >= KTOP) {
            unsigned cum = excl;
            for (int bb = tid * 16 + 15; bb >= tid * 16; bb--) {
                cum += histM[bb];
                if (cum >= KTOP) {
                    s_binT = (unsigned)bb; s_above = cum - histM[bb]; s_found = 1;
                    break;
                }
            }
        }
        __syncthreads();
        const unsigned bT = s_binT;
        for (int p = tid; p < PRI; p += 256) {
            unsigned bits = col[(size_t)p * NCLS_TOT];
            if (__uint_as_float(bits) > CONF_TH && (bits >> 20) >= bT) {
                unsigned pos = atomicAdd(&s_gc, 1u);
                if (pos < CAND_MAX)
                    buf[pos] = ((unsigned long long)bits << 32) | (unsigned)(~(unsigned)p);
            }
        }
        __syncthreads();
        gcount = (int)min(s_gc, (unsigned)CAND_MAX);
        histM[tid] = 0;
        __syncthreads();
    }

    const int found = s_found;
    const unsigned binT = s_binT;
    const unsigned need = KTOP - s_above;

    // ---- fine refinement: bits[19:12] within cut bin ----
    if (found && !skipRef) {
        for (int t = tid; t < gcount; t += 256) {
            unsigned long long key = buf[t];
            if ((unsigned)(key >> 52) == binT)
                atomicAdd(&histM[(unsigned)(key >> 44) & 0xFFu], 1u);
        }
        __syncthreads();
        unsigned part = histM[tid];
        unsigned incl = suffix_incl_256(part, warpTot, lane, wid);
        unsigned excl = incl - part;
        if (excl < need && incl >= need) {
            s_fcut = (unsigned)tid; s_aboveF = excl; s_cntF = part;
        }
        __syncthreads();
    }
    const unsigned fcut = s_fcut;                     // 0 when skipRef

    // ---- optional fine2 on bits[11:4] ----
    if (found && !skipRef && (s_aboveF + s_cntF > CAND2)) {
        const unsigned need2 = need - s_aboveF;
        histM[tid] = 0;
        __syncthreads();
        for (int t = tid; t < gcount; t += 256) {
            unsigned long long key = buf[t];
            if ((unsigned)(key >> 52) == binT &&
                ((unsigned)(key >> 44) & 0xFFu) == fcut)
                atomicAdd(&histM[(unsigned)(key >> 36) & 0xFFu], 1u);
        }
        __syncthreads();
        unsigned part = histM[tid];
        unsigned incl = suffix_incl_256(part, warpTot, lane, wid);
        unsigned excl = incl - part;
        if (excl < need2 && incl >= need2) s_f2cut = (unsigned)tid;
        __syncthreads();
    }
    const unsigned f2cut = s_f2cut;
    __syncthreads();

    // ---- compact refined candidates into cand2 ----
    cand2[tid] = 0ULL;
    __syncthreads();
    for (int t = tid; t < gcount; t += 256) {
        unsigned long long key = buf[t];
        unsigned cb = (unsigned)(key >> 52);
        unsigned fb = (unsigned)(key >> 44) & 0xFFu;
        unsigned f2 = (unsigned)(key >> 36) & 0xFFu;
        if (cb > binT ||
            (cb == binT && (fb > fcut || (fb == fcut && f2 >= f2cut)))) {
            unsigned pos = atomicAdd(&s_n2, 1u);
            if (pos < CAND2) cand2[pos] = key;
        }
    }
    __syncthreads();
    const int n = min((int)min(s_n2, (unsigned)CAND2), KTOP);

    // ---- register bitonic sort (asc) ----
    unsigned long long key = cand2[tid];
    for (int kk = 2; kk <= 256; kk <<= 1) {
        bool up = ((tid & kk) == 0);
        for (int jj = kk >> 1; jj > 0; jj >>= 1) {
            unsigned long long partner;
            if (jj >= 32) {
                __syncthreads();
                cand2[tid] = key;
                __syncthreads();
                partner = cand2[tid ^ jj];
            } else {
                partner = __shfl_xor_sync(0xFFFFFFFFu, key, jj);
            }
            bool takeMin = (((tid & jj) == 0) == up);
            bool sw = takeMin ? (partner < key) : (partner > key);
            if (sw) key = partner;
        }
    }
    __syncthreads();

    // ---- extract top-n (descending); zero mask rows ----
    {
        int k = 255 - tid;
        if (k < n) {
            unsigned bits = (unsigned)(key >> 32);
            int p = (int)(~(unsigned)key);
            float4 bx = g_boxes[b * PRI + p];
            sBox[k]   = bx;
            sScore[k] = __uint_as_float(bits);
            sTArea[k] = NMS_TH * (bx.z - bx.x) * (bx.w - bx.y);
        }
        for (int t = tid; t < n * 8; t += 256) maskW[t] = 0u;
    }
    __syncthreads();

    // ---- suppression bitmask: w-outer, bj pinned in regs, 4 rows/inner ----
    const int wEnd = (n + 31) >> 5;
    const float Tp1 = 1.0f + NMS_TH;
    for (int w = 0; w < wEnd; w++) {
        const int j = w * 32 + lane;
        const bool jv = (j < n);
        float4 bj = make_float4(0.f, 0.f, 0.f, 0.f);
        float nTj = 0.f;
        if (jv) { bj = sBox[j]; nTj = -sTArea[j]; }
        const int iMax = min(n, w * 32 + 32);      // rows needing word w: i < iMax
        for (int i0 = wid * 4; i0 < iMax; i0 += 32) {
            #pragma unroll
            for (int r = 0; r < 4; r++) {
                const int i = i0 + r;
                const bool iv = (i < iMax);
                bool sup = false;
                if (iv) {
                    float4 bi = sBox[i];
                    float nTi = -sTArea[i];
                    if (jv && j > i) {
                        float ww = fminf(bi.z, bj.z) - fmaxf(bi.x, bj.x);
                        float hh = fminf(bi.w, bj.w) - fmaxf(bi.y, bj.y);
                        ww = fmaxf(ww, 0.0f); hh = fmaxf(hh, 0.0f);
                        sup = fmaf(ww * hh, Tp1, nTi + nTj) > 0.0f;
                    }
                }
                unsigned bal = __ballot_sync(0xFFFFFFFFu, sup);
                if (lane == 0 && iv) maskW[i * 8 + w] = bal;
            }
        }
    }
    __syncthreads();

    // ---- greedy scan (tid 0) overlapped with slab zero (warps 1-7) ----
    float* outBase = out + (size_t)(b * NCLS_TOT + cc + 1) * KTOP * 5;
    float4* outBase4 = (float4*)outBase;
    if (tid == 0) {
        const unsigned long long* m64 = (const unsigned long long*)maskW;
        unsigned long long kw[4];
        #pragma unroll
        for (int q = 0; q < 4; q++) {
            int rem = n - q * 64;
            kw[q] = (rem >= 64) ? ~0ULL : (rem > 0 ? ((1ULL << rem) - 1ULL) : 0ULL);
        }
        #pragma unroll
        for (int q = 0; q < 4; q++) {
            unsigned long long w = kw[q];
            while (w) {
                int bit = __ffsll((long long)w) - 1;
                int i = q * 64 + bit;
                kw[0] &= ~m64[i * 4 + 0]; kw[1] &= ~m64[i * 4 + 1];
                kw[2] &= ~m64[i * 4 + 2]; kw[3] &= ~m64[i * 4 + 3];
                unsigned long long hi = (bit == 63) ? 0ULL : (~0ULL << (bit + 1));
                w = kw[q] & hi;
            }
        }
        sKeepW[0] = kw[0]; sKeepW[1] = kw[1]; sKeepW[2] = kw[2]; sKeepW[3] = kw[3];
    } else if (tid >= 32) {
        for (int t = tid - 32; t < KTOP * 5 / 4; t += 224)
            outBase4[t] = make_float4(0.f, 0.f, 0.f, 0.f);
    }
    __syncthreads();

    // ---- scatter kept rows to front ----
    for (int k = tid; k < n; k += 256) {
        unsigned long long w = sKeepW[k >> 6];
        if ((w >> (k & 63)) & 1ULL) {
            int d = 0;
            for (int q = 0; q < (k >> 6); q++) d += __popcll(sKeepW[q]);
            unsigned long long below = (k & 63) ? (w & ((1ULL << (k & 63)) - 1ULL)) : 0ULL;
            d += __popcll(below);
            float* r = outBase + d * 5;
            float4 bx = sBox[k];
            r[0] = sScore[k];
            r[1] = bx.x; r[2] = bx.y; r[3] = bx.z; r[4] = bx.w;
        }
    }
}

// ---------------------------------------------------------------------------
extern "C" void kernel_launch(void* const* d_in, const int* in_sizes, int n_in,
                              void* d_out, int out_size) {
    const float4*   loc   = (const float4*)d_in[0];     // [B, P, 4]
    const unsigned* conf  = (const unsigned*)d_in[1];   // [B*P, C] (float bits)
    const float4*   prior = (const float4*)d_in[2];     // [P, 4]
    float* out = (float*)d_out;                         // [B, C, K, 5]

    prep_kernel<<<(BATCH * PRI + 255) / 256, 256>>>(loc, prior, out);

    dim3 fg(NCHUNK, BATCH);
    filter_kernel<<<fg, 256>>>(conf);

    nms_kernel<<<NTASK, 256>>>(conf, out);
}